// round 1
// baseline (speedup 1.0000x reference)
#include <cuda_runtime.h>
#include <cstdint>

// Problem constants
#define NUM_PROPERTIES 10000
#define HDIM 512
#define ODIM 2
#define BATCH 512
#define NUM_PROPS 128
#define NROWS (BATCH * NUM_PROPS)   // 65536 (b,p) rows

// Flag: 1 if properties buffer is int64, 0 if int32. Set each launch by a
// tiny detection kernel (deterministic: same input -> same flag).
__device__ int g_idx_is_64;

__global__ void detect_idx_dtype_kernel(const int* __restrict__ p32) {
    if (threadIdx.x == 0 && blockIdx.x == 0) {
        const long long* p64 = (const long long*)p32;
        int is64 = 1;
        #pragma unroll 1
        for (int i = 0; i < 64; i++) {
            long long v = p64[i];
            if (v < 0 || v >= NUM_PROPERTIES) { is64 = 0; break; }
        }
        g_idx_is_64 = is64;
    }
}

// One warp per (b,p) row.
// h row: 512 f32 = 128 float4; lane handles float4 indices {lane + 32k}, k=0..3.
// W row ([HDIM, 2] row-major): h-chunk m (4 h-elems) pairs with W float4s 2m, 2m+1:
//   W4[2m]   = (W[4m+0][0], W[4m+0][1], W[4m+1][0], W[4m+1][1])
//   W4[2m+1] = (W[4m+2][0], W[4m+2][1], W[4m+3][0], W[4m+3][1])
__global__ __launch_bounds__(256, 8)
void adapter_gemv_kernel(
    const float*  __restrict__ hs,     // (B, P, H)
    const int*    __restrict__ props,  // (B, P) int32 or int64 (see flag)
    const float*  __restrict__ mask,   // (B, P)
    const float*  __restrict__ W,      // (NUM_PROPERTIES, H, 2)
    const float*  __restrict__ bias,   // (NUM_PROPERTIES, 2)
    float*        __restrict__ out)    // (B, P, 2)
{
    const int gwarp = (blockIdx.x * blockDim.x + threadIdx.x) >> 5;
    const int lane  = threadIdx.x & 31;
    if (gwarp >= NROWS) return;

    long long prop;
    if (g_idx_is_64) prop = ((const long long*)props)[gwarp];
    else             prop = (long long)props[gwarp];

    const float4* __restrict__ h4 = (const float4*)(hs + (size_t)gwarp * HDIM);
    const float4* __restrict__ w4 = (const float4*)(W + (size_t)prop * (HDIM * ODIM));

    float acc0 = 0.0f, acc1 = 0.0f;
    #pragma unroll
    for (int k = 0; k < 4; k++) {
        const int m = lane + 32 * k;
        const float4 h = h4[m];
        const float4 a = w4[2 * m + 0];
        const float4 b = w4[2 * m + 1];
        acc0 = fmaf(h.x, a.x, acc0);
        acc1 = fmaf(h.x, a.y, acc1);
        acc0 = fmaf(h.y, a.z, acc0);
        acc1 = fmaf(h.y, a.w, acc1);
        acc0 = fmaf(h.z, b.x, acc0);
        acc1 = fmaf(h.z, b.y, acc1);
        acc0 = fmaf(h.w, b.z, acc0);
        acc1 = fmaf(h.w, b.w, acc1);
    }

    #pragma unroll
    for (int off = 16; off > 0; off >>= 1) {
        acc0 += __shfl_xor_sync(0xffffffff, acc0, off);
        acc1 += __shfl_xor_sync(0xffffffff, acc1, off);
    }

    if (lane == 0) {
        const float m  = mask[gwarp];
        const float b0 = bias[prop * 2 + 0];
        const float b1 = bias[prop * 2 + 1];
        float2 r;
        r.x = (acc0 + b0) * m;
        r.y = (acc1 + b1) * m;
        ((float2*)out)[gwarp] = r;
    }
}

extern "C" void kernel_launch(void* const* d_in, const int* in_sizes, int n_in,
                              void* d_out, int out_size) {
    const float* hs    = (const float*)d_in[0];   // hidden_states (512,128,512) f32
    const int*   props = (const int*)d_in[1];     // properties (512,128) int32/int64
    const float* mask  = (const float*)d_in[2];   // mask (512,128) f32
    const float* W     = (const float*)d_in[3];   // classifier_weights (10000,512,2) f32
    const float* bias  = (const float*)d_in[4];   // classifier_bias (10000,2) f32
    float*       out   = (float*)d_out;           // (512,128,2) f32

    detect_idx_dtype_kernel<<<1, 32>>>(props);

    const int threads = 256;                       // 8 warps/block
    const int blocks  = NROWS / (threads / 32);    // 8192
    adapter_gemv_kernel<<<blocks, threads>>>(hs, props, mask, W, bias, out);
}

// round 2
// speedup vs baseline: 1.0544x; 1.0544x over previous
#include <cuda_runtime.h>
#include <cstdint>

// Problem constants
#define NUM_PROPERTIES 10000
#define HDIM 512
#define ODIM 2
#define BATCH 512
#define NUM_PROPS 128
#define NROWS (BATCH * NUM_PROPS)   // 65536 (b,p) rows

// Flag: 1 if properties buffer is int64, 0 if int32. Set each launch by a
// tiny detection kernel (deterministic: same input -> same flag).
__device__ int g_idx_is_64;

__global__ void detect_idx_dtype_kernel(const int* __restrict__ p32) {
    // 32 lanes each check 2 values -> 64 values, independent loads (no serial
    // dependence chain), ballot-combine.
    const long long* p64 = (const long long*)p32;
    int lane = threadIdx.x & 31;
    bool ok = true;
    #pragma unroll
    for (int k = 0; k < 2; k++) {
        long long v = p64[lane + 32 * k];
        ok &= (v >= 0 && v < NUM_PROPERTIES);
    }
    unsigned m = __ballot_sync(0xffffffffu, ok);
    if (lane == 0) g_idx_is_64 = (m == 0xffffffffu) ? 1 : 0;
}

__device__ __forceinline__ float4 ldcs_f4(const float4* p) {
    float4 v;
    asm volatile("ld.global.cs.v4.f32 {%0,%1,%2,%3}, [%4];"
                 : "=f"(v.x), "=f"(v.y), "=f"(v.z), "=f"(v.w) : "l"(p));
    return v;
}

// One warp per (b,p) row.
// h row: 512 f32 = 128 float4; lane handles float4 indices {lane + 32k}, k=0..3.
//   hidden_states is streamed with evict-first (.cs) so the 40 MiB W table
//   stays resident in L2 (it is reused ~6.5x per launch).
// W row ([HDIM, 2] row-major): h-chunk m (4 h-elems) pairs with W float4s 2m, 2m+1.
__global__ __launch_bounds__(256, 8)
void adapter_gemv_kernel(
    const float*  __restrict__ hs,     // (B, P, H)
    const int*    __restrict__ props,  // (B, P) int32 or int64 (see flag)
    const float*  __restrict__ mask,   // (B, P)
    const float*  __restrict__ W,      // (NUM_PROPERTIES, H, 2)
    const float*  __restrict__ bias,   // (NUM_PROPERTIES, 2)
    float*        __restrict__ out)    // (B, P, 2)
{
    const int gwarp = (blockIdx.x * blockDim.x + threadIdx.x) >> 5;
    const int lane  = threadIdx.x & 31;
    if (gwarp >= NROWS) return;

    long long prop;
    if (g_idx_is_64) prop = ((const long long*)props)[gwarp];
    else             prop = (long long)props[gwarp];

    const float4* __restrict__ h4 = (const float4*)(hs + (size_t)gwarp * HDIM);
    const float4* __restrict__ w4 = (const float4*)(W + (size_t)prop * (HDIM * ODIM));

    float acc0 = 0.0f, acc1 = 0.0f;
    #pragma unroll
    for (int k = 0; k < 4; k++) {
        const int m = lane + 32 * k;
        const float4 h = ldcs_f4(&h4[m]);       // streaming: evict-first
        const float4 a = w4[2 * m + 0];         // default: keep in L2
        const float4 b = w4[2 * m + 1];
        acc0 = fmaf(h.x, a.x, acc0);
        acc1 = fmaf(h.x, a.y, acc1);
        acc0 = fmaf(h.y, a.z, acc0);
        acc1 = fmaf(h.y, a.w, acc1);
        acc0 = fmaf(h.z, b.x, acc0);
        acc1 = fmaf(h.z, b.y, acc1);
        acc0 = fmaf(h.w, b.z, acc0);
        acc1 = fmaf(h.w, b.w, acc1);
    }

    #pragma unroll
    for (int off = 16; off > 0; off >>= 1) {
        acc0 += __shfl_xor_sync(0xffffffff, acc0, off);
        acc1 += __shfl_xor_sync(0xffffffff, acc1, off);
    }

    if (lane == 0) {
        const float m  = mask[gwarp];
        const float b0 = bias[prop * 2 + 0];
        const float b1 = bias[prop * 2 + 1];
        float2 r;
        r.x = (acc0 + b0) * m;
        r.y = (acc1 + b1) * m;
        asm volatile("st.global.cs.v2.f32 [%0], {%1,%2};"
                     :: "l"(((float2*)out) + gwarp), "f"(r.x), "f"(r.y));
    }
}

extern "C" void kernel_launch(void* const* d_in, const int* in_sizes, int n_in,
                              void* d_out, int out_size) {
    const float* hs    = (const float*)d_in[0];   // hidden_states (512,128,512) f32
    const int*   props = (const int*)d_in[1];     // properties (512,128) int32/int64
    const float* mask  = (const float*)d_in[2];   // mask (512,128) f32
    const float* W     = (const float*)d_in[3];   // classifier_weights (10000,512,2) f32
    const float* bias  = (const float*)d_in[4];   // classifier_bias (10000,2) f32
    float*       out   = (float*)d_out;           // (512,128,2) f32

    detect_idx_dtype_kernel<<<1, 32>>>(props);

    const int threads = 256;                       // 8 warps/block
    const int blocks  = NROWS / (threads / 32);    // 8192
    adapter_gemv_kernel<<<blocks, threads>>>(hs, props, mask, W, bias, out);
}

// round 3
// speedup vs baseline: 1.1311x; 1.0727x over previous
#include <cuda_runtime.h>
#include <cstdint>

// Problem constants
#define NUM_PROPERTIES 10000
#define HDIM 512
#define ODIM 2
#define BATCH 512
#define NUM_PROPS 128
#define NROWS (BATCH * NUM_PROPS)   // 65536 (b,p) rows

// Flag: 1 if properties buffer is int64, 0 if int32. Set each launch by a
// tiny detection kernel (deterministic: same input -> same flag).
__device__ int g_idx_is_64;

__global__ void detect_idx_dtype_kernel(const int* __restrict__ p32) {
    const long long* p64 = (const long long*)p32;
    int lane = threadIdx.x & 31;
    bool ok = true;
    #pragma unroll
    for (int k = 0; k < 2; k++) {
        long long v = p64[lane + 32 * k];
        ok &= (v >= 0 && v < NUM_PROPERTIES);
    }
    unsigned m = __ballot_sync(0xffffffffu, ok);
    if (lane == 0) g_idx_is_64 = (m == 0xffffffffu) ? 1 : 0;
}

__device__ __forceinline__ float2 ldcs_f2(const float2* p) {
    float2 v;
    asm volatile("ld.global.cs.v2.f32 {%0,%1}, [%2];"
                 : "=f"(v.x), "=f"(v.y) : "l"(p));
    return v;
}

// One warp per (b,p) row; dot product partitioned across lanes by W-float4
// index so that BOTH streams are fully coalesced:
//   W row = 256 float4; W4[j] = (W[2j][0], W[2j][1], W[2j+1][0], W[2j+1][1])
//   h row = 256 float2; h2[j] pairs with W4[j].
//   lane handles j = lane + 32k, k = 0..7:
//     W loads: warp covers 512B contiguous (4 wavefronts, minimum)
//     h loads: warp covers 256B contiguous (2 wavefronts, minimum)
// (Previous layout had 32B-strided W loads -> 2x L1 wavefronts.)
// hidden_states streamed evict-first (.cs) so the 40 MiB W table stays in L2.
__global__ __launch_bounds__(256, 8)
void adapter_gemv_kernel(
    const float*  __restrict__ hs,     // (B, P, H)
    const int*    __restrict__ props,  // (B, P) int32 or int64 (see flag)
    const float*  __restrict__ mask,   // (B, P)
    const float*  __restrict__ W,      // (NUM_PROPERTIES, H, 2)
    const float*  __restrict__ bias,   // (NUM_PROPERTIES, 2)
    float*        __restrict__ out)    // (B, P, 2)
{
    const int gwarp = (blockIdx.x * blockDim.x + threadIdx.x) >> 5;
    const int lane  = threadIdx.x & 31;
    if (gwarp >= NROWS) return;

    long long prop;
    if (g_idx_is_64) prop = ((const long long*)props)[gwarp];
    else             prop = (long long)props[gwarp];

    const float2* __restrict__ h2 = (const float2*)(hs + (size_t)gwarp * HDIM);
    const float4* __restrict__ w4 = (const float4*)(W + (size_t)prop * (HDIM * ODIM));

    float acc0 = 0.0f, acc1 = 0.0f;
    #pragma unroll 4
    for (int k = 0; k < 8; k++) {
        const int j = lane + 32 * k;
        const float2 h = ldcs_f2(&h2[j]);   // streaming: evict-first
        const float4 w = w4[j];             // default: keep in L2
        acc0 = fmaf(h.x, w.x, acc0);
        acc1 = fmaf(h.x, w.y, acc1);
        acc0 = fmaf(h.y, w.z, acc0);
        acc1 = fmaf(h.y, w.w, acc1);
    }

    #pragma unroll
    for (int off = 16; off > 0; off >>= 1) {
        acc0 += __shfl_xor_sync(0xffffffff, acc0, off);
        acc1 += __shfl_xor_sync(0xffffffff, acc1, off);
    }

    if (lane == 0) {
        const float m  = mask[gwarp];
        const float b0 = bias[prop * 2 + 0];
        const float b1 = bias[prop * 2 + 1];
        float2 r;
        r.x = (acc0 + b0) * m;
        r.y = (acc1 + b1) * m;
        asm volatile("st.global.cs.v2.f32 [%0], {%1,%2};"
                     :: "l"(((float2*)out) + gwarp), "f"(r.x), "f"(r.y));
    }
}

extern "C" void kernel_launch(void* const* d_in, const int* in_sizes, int n_in,
                              void* d_out, int out_size) {
    const float* hs    = (const float*)d_in[0];   // hidden_states (512,128,512) f32
    const int*   props = (const int*)d_in[1];     // properties (512,128) int32/int64
    const float* mask  = (const float*)d_in[2];   // mask (512,128) f32
    const float* W     = (const float*)d_in[3];   // classifier_weights (10000,512,2) f32
    const float* bias  = (const float*)d_in[4];   // classifier_bias (10000,2) f32
    float*       out   = (float*)d_out;           // (512,128,2) f32

    detect_idx_dtype_kernel<<<1, 32>>>(props);

    const int threads = 256;                       // 8 warps/block
    const int blocks  = NROWS / (threads / 32);    // 8192
    adapter_gemv_kernel<<<blocks, threads>>>(hs, props, mask, W, bias, out);
}

// round 4
// speedup vs baseline: 1.2119x; 1.0714x over previous
#include <cuda_runtime.h>
#include <cstdint>

// Problem constants
#define NUM_PROPERTIES 10000
#define HDIM 512
#define ODIM 2
#define BATCH 512
#define NUM_PROPS 128
#define NROWS (BATCH * NUM_PROPS)   // 65536 (b,p) rows

#define NSM 148
#define CTAS_PER_SM 8
#define GRID_CTAS (NSM * CTAS_PER_SM)          // 1184
#define WARPS_PER_CTA 8
#define TOTAL_WARPS (GRID_CTAS * WARPS_PER_CTA) // 9472

__device__ __forceinline__ float2 ldcs_f2(const float2* p) {
    float2 v;
    asm volatile("ld.global.cs.v2.f32 {%0,%1}, [%2];"
                 : "=f"(v.x), "=f"(v.y) : "l"(p));
    return v;
}

// Persistent grid-stride kernel; one warp per (b,p) row per iteration.
//
// Dtype self-detection (properties may be int32 or int64 depending on JAX
// x64 config): every warp reads p64[lane] (the first 256 bytes, in-bounds
// under BOTH interpretations since the buffer is >= 256 KiB) and ballots
// whether all 32 values lie in [0, NUM_PROPERTIES). If the data is int32,
// that requires 32 consecutive odd-index props to be zero (~1e-128 for
// uniform [0,10000) indices). Deterministic: same input -> same flag, and
// identical across all warps. The window is L1/L2-resident after warp 0.
//
// Memory layout per row (wavefront-minimal, see R3):
//   W row = 256 float4; lane handles j = lane + 32k, k = 0..7 (contiguous
//   warp-wide); h row = 256 float2 paired 1:1 with W float4s.
// hidden_states + out use evict-first (.cs) so the 40 MiB W table stays in L2.
__global__ __launch_bounds__(256, CTAS_PER_SM)
void adapter_gemv_kernel(
    const float*  __restrict__ hs,     // (B, P, H)
    const int*    __restrict__ props,  // (B, P) int32 or int64 (detected)
    const float*  __restrict__ mask,   // (B, P)
    const float*  __restrict__ W,      // (NUM_PROPERTIES, H, 2)
    const float*  __restrict__ bias,   // (NUM_PROPERTIES, 2)
    float*        __restrict__ out)    // (B, P, 2)
{
    const int lane   = threadIdx.x & 31;
    const int gwarp0 = (blockIdx.x * blockDim.x + threadIdx.x) >> 5;

    // --- per-warp dtype detection (one broadcast 256B window) ---
    const long long* p64 = (const long long*)props;
    long long probe = p64[lane];
    bool in_range = (probe >= 0) && (probe < NUM_PROPERTIES);
    const bool is64 = (__ballot_sync(0xffffffffu, in_range) == 0xffffffffu);

    for (int row = gwarp0; row < NROWS; row += TOTAL_WARPS) {
        long long prop;
        if (is64) prop = p64[row];
        else      prop = (long long)props[row];

        const float2* __restrict__ h2 = (const float2*)(hs + (size_t)row * HDIM);
        const float4* __restrict__ w4 = (const float4*)(W + (size_t)prop * (HDIM * ODIM));

        float acc0 = 0.0f, acc1 = 0.0f;
        #pragma unroll 4
        for (int k = 0; k < 8; k++) {
            const int j = lane + 32 * k;
            const float2 h = ldcs_f2(&h2[j]);   // streaming: evict-first
            const float4 w = w4[j];             // default: keep in L2
            acc0 = fmaf(h.x, w.x, acc0);
            acc1 = fmaf(h.x, w.y, acc1);
            acc0 = fmaf(h.y, w.z, acc0);
            acc1 = fmaf(h.y, w.w, acc1);
        }

        #pragma unroll
        for (int off = 16; off > 0; off >>= 1) {
            acc0 += __shfl_xor_sync(0xffffffff, acc0, off);
            acc1 += __shfl_xor_sync(0xffffffff, acc1, off);
        }

        if (lane == 0) {
            const float m  = mask[row];
            const float b0 = bias[prop * 2 + 0];
            const float b1 = bias[prop * 2 + 1];
            float2 r;
            r.x = (acc0 + b0) * m;
            r.y = (acc1 + b1) * m;
            asm volatile("st.global.cs.v2.f32 [%0], {%1,%2};"
                         :: "l"(((float2*)out) + row), "f"(r.x), "f"(r.y));
        }
    }
}

extern "C" void kernel_launch(void* const* d_in, const int* in_sizes, int n_in,
                              void* d_out, int out_size) {
    const float* hs    = (const float*)d_in[0];   // hidden_states (512,128,512) f32
    const int*   props = (const int*)d_in[1];     // properties (512,128)
    const float* mask  = (const float*)d_in[2];   // mask (512,128) f32
    const float* W     = (const float*)d_in[3];   // classifier_weights (10000,512,2) f32
    const float* bias  = (const float*)d_in[4];   // classifier_bias (10000,2) f32
    float*       out   = (float*)d_out;           // (512,128,2) f32

    adapter_gemv_kernel<<<GRID_CTAS, 256>>>(hs, props, mask, W, bias, out);
}